// round 1
// baseline (speedup 1.0000x reference)
#include <cuda_runtime.h>
#include <math.h>

#define Bq 2
#define Lq 5
#define Nq 10
#define Cq 64
#define Hq 128
#define Wq 256
#define HWq (Hq * Wq)          // 32768
#define NHWq (Nq * HWq)        // 327680
#define OUTQ (Bq * Cq * HWq)   // 4194304

// ---------------- scratch (no allocations allowed) ----------------
__device__ float g_conf[NHWq];
__device__ float g_mask[NHWq];
__device__ float g_sum[Bq * Cq];
__device__ float g_maxv[Bq * Cq];
__device__ float g_gate[Bq * Cq];
__device__ unsigned int g_count;

// 5x5 Gaussian, sigma=1, 1/(2*pi*sigma) * exp(-(dx^2+dy^2)/2)  (NOT normalized, matches ref)
__constant__ float GK[25] = {
    0.0029150243f, 0.0130642333f, 0.0215392793f, 0.0130642333f, 0.0029150243f,
    0.0130642333f, 0.0585498315f, 0.0965323526f, 0.0585498315f, 0.0130642333f,
    0.0215392793f, 0.0965323526f, 0.1591549431f, 0.0965323526f, 0.0215392793f,
    0.0130642333f, 0.0585498315f, 0.0965323526f, 0.0585498315f, 0.0130642333f,
    0.0029150243f, 0.0130642333f, 0.0215392793f, 0.0130642333f, 0.0029150243f
};

__device__ __forceinline__ float sigmoidf_(float x) { return 1.0f / (1.0f + expf(-x)); }

__device__ __forceinline__ void atomicMaxFloat(float* addr, float v) {
    int old = __float_as_int(*addr);
    while (__int_as_float(old) < v) {
        int assumed = old;
        old = atomicCAS((int*)addr, assumed, __float_as_int(v));
        if (old == assumed) break;
    }
}

// ---------------- kernel 1: confidence map + scratch re-init ----------------
__global__ void conf_kernel(const float* __restrict__ psm,
                            const float* __restrict__ inv_delay,
                            const float* __restrict__ ewc_w,
                            const float* __restrict__ ewc_b) {
    int i = blockIdx.x * blockDim.x + threadIdx.x;
    if (blockIdx.x == 0) {
        if (threadIdx.x < Bq * Cq) {
            g_sum[threadIdx.x]  = 0.0f;
            g_maxv[threadIdx.x] = -INFINITY;
        }
        if (threadIdx.x == 0) g_count = 0u;
    }
    if (i >= NHWq) return;
    int n = i / HWq;
    int p = i - n * HWq;
    float enc = tanhf(inv_delay[n] * ewc_w[0] + ewc_b[0]) + 1.0f;
    float a = psm[(n * 2 + 0) * HWq + p];
    float b = psm[(n * 2 + 1) * HWq + p];
    g_conf[i] = fmaxf(sigmoidf_(a), sigmoidf_(b)) * enc;
}

// ---------------- kernel 2: 5x5 gaussian + threshold + ego + count ----------------
__global__ void mask_kernel() {
    int i = blockIdx.x * blockDim.x + threadIdx.x;   // NHWq divisible by 256: no divergence
    int n = i / HWq;
    int p = i - n * HWq;
    int h = p / Wq;
    int w = p - h * Wq;
    const float* cn = g_conf + n * HWq;
    float acc = 0.0f;
#pragma unroll
    for (int dy = -2; dy <= 2; dy++) {
        int hh = h + dy;
        if (hh < 0 || hh >= Hq) continue;
#pragma unroll
        for (int dx = -2; dx <= 2; dx++) {
            int ww = w + dx;
            if (ww < 0 || ww >= Wq) continue;
            acc += GK[(dy + 2) * 5 + (dx + 2)] * cn[hh * Wq + ww];
        }
    }
    float m = (acc > 0.01f) ? 1.0f : 0.0f;
    if (n % Lq == 0) m = 1.0f;   // ego always communicates
    g_mask[i] = m;
    unsigned bal = __ballot_sync(0xffffffffu, m > 0.5f);
    if ((threadIdx.x & 31) == 0) atomicAdd(&g_count, (unsigned)__popc(bal));
}

// ---------------- kernel 3: per-pixel cross-agent attention + pooling ----------------
__global__ void __launch_bounds__(256) fuse_kernel(
        const float* __restrict__ x,
        const float* __restrict__ inv_delay,
        const float* __restrict__ ew_w,
        const float* __restrict__ ew_b,
        float* __restrict__ out) {
    int b    = blockIdx.y;
    int p    = blockIdx.x * blockDim.x + threadIdx.x;   // pixel 0..HWq-1
    int wid  = threadIdx.x >> 5;
    int lane = threadIdx.x & 31;

    __shared__ float s_wsum[Cq * 8];
    __shared__ float s_wmax[Cq * 8];

    float eww = ew_w[0], ewb = ew_b[0];

    float s[Lq];
    const float* xb[Lq];
#pragma unroll
    for (int l = 0; l < Lq; l++) {
        int n = b * Lq + l;
        float enw = tanhf(inv_delay[n] * eww + ewb) + 1.0f;
        s[l] = enw * g_mask[n * HWq + p];   // ego mask already forced to 1
        xb[l] = x + (size_t)(n * Cq) * HWq + p;
    }

    // pass 1: raw dot products ego . feat_l
    float dot[Lq] = {0.f, 0.f, 0.f, 0.f, 0.f};
#pragma unroll 4
    for (int c = 0; c < Cq; c++) {
        float ego = xb[0][c * HWq];
        dot[0] += ego * ego;
#pragma unroll
        for (int l = 1; l < Lq; l++) dot[l] += ego * xb[l][c * HWq];
    }

    // scores with folded scaling, softmax over L
    float sc[Lq], mx = -INFINITY;
#pragma unroll
    for (int l = 0; l < Lq; l++) {
        sc[l] = dot[l] * s[0] * s[l] * 0.125f;   // 1/sqrt(64)
        mx = fmaxf(mx, sc[l]);
    }
    float esum = 0.0f;
#pragma unroll
    for (int l = 0; l < Lq; l++) { sc[l] = expf(sc[l] - mx); esum += sc[l]; }
    float inv = 1.0f / esum;
    float coef[Lq];
#pragma unroll
    for (int l = 0; l < Lq; l++) coef[l] = sc[l] * inv * s[l];

    // pass 2: fused output + per-channel pooling (warp reduce)
    float* ob = out + (size_t)(b * Cq) * HWq + p;
#pragma unroll 4
    for (int c = 0; c < Cq; c++) {
        float f = coef[0] * xb[0][c * HWq];
#pragma unroll
        for (int l = 1; l < Lq; l++) f += coef[l] * xb[l][c * HWq];
        ob[c * HWq] = f;
        float ws = f, wm = f;
#pragma unroll
        for (int o = 16; o > 0; o >>= 1) {
            ws += __shfl_xor_sync(0xffffffffu, ws, o);
            wm = fmaxf(wm, __shfl_xor_sync(0xffffffffu, wm, o));
        }
        if (lane == 0) { s_wsum[c * 8 + wid] = ws; s_wmax[c * 8 + wid] = wm; }
    }
    __syncthreads();

    int t = threadIdx.x;
    if (t < Cq) {
        float acc = 0.0f;
#pragma unroll
        for (int k = 0; k < 8; k++) acc += s_wsum[t * 8 + k];
        atomicAdd(&g_sum[b * Cq + t], acc);
    } else if (t < 2 * Cq) {
        int c = t - Cq;
        float acc = -INFINITY;
#pragma unroll
        for (int k = 0; k < 8; k++) acc = fmaxf(acc, s_wmax[c * 8 + k]);
        atomicMaxFloat(&g_maxv[b * Cq + c], acc);
    }
}

// ---------------- kernel 4: channel gate MLP + comm_rate ----------------
__global__ void gate_kernel(const float* __restrict__ w1,   // (4,64) row-major
                            const float* __restrict__ w2,   // (64,4) row-major
                            float* __restrict__ out, int out_size) {
    __shared__ float s_avg[Bq][Cq];
    __shared__ float s_mx[Bq][Cq];
    int t = threadIdx.x;            // 0..127
    int b = t / Cq, c = t - b * Cq;
    s_avg[b][c] = g_sum[t] * (1.0f / HWq);
    s_mx[b][c]  = g_maxv[t];
    __syncthreads();

    float ha[4], hm[4];
#pragma unroll
    for (int j = 0; j < 4; j++) {
        float sa = 0.0f, sm = 0.0f;
        for (int cc = 0; cc < Cq; cc++) {
            float w = w1[j * Cq + cc];
            sa += s_avg[b][cc] * w;
            sm += s_mx[b][cc] * w;
        }
        ha[j] = fmaxf(sa, 0.0f);
        hm[j] = fmaxf(sm, 0.0f);
    }
    float oa = 0.0f, om = 0.0f;
#pragma unroll
    for (int j = 0; j < 4; j++) {
        float w = w2[c * 4 + j];
        oa += ha[j] * w;
        om += hm[j] * w;
    }
    g_gate[t] = sigmoidf_(oa + om);

    if (t == 0 && out_size > OUTQ)
        out[out_size - 1] = (float)g_count / (float)NHWq;
}

// ---------------- kernel 5: apply channel gate ----------------
__global__ void scale_kernel(float* __restrict__ out) {
    int i = blockIdx.x * blockDim.x + threadIdx.x;
    if (i >= OUTQ) return;
    out[i] *= g_gate[i / HWq];
}

// ---------------- launch ----------------
extern "C" void kernel_launch(void* const* d_in, const int* in_sizes, int n_in,
                              void* d_out, int out_size) {
    const float* x         = (const float*)d_in[0];
    const float* psm       = (const float*)d_in[1];
    const float* inv_delay = (const float*)d_in[2];
    const float* ew_w      = (const float*)d_in[3];
    const float* ew_b      = (const float*)d_in[4];
    const float* ewc_w     = (const float*)d_in[5];
    const float* ewc_b     = (const float*)d_in[6];
    const float* sta_w1    = (const float*)d_in[7];
    const float* sta_w2    = (const float*)d_in[8];
    float* out = (float*)d_out;

    conf_kernel<<<NHWq / 256, 256>>>(psm, inv_delay, ewc_w, ewc_b);
    mask_kernel<<<NHWq / 256, 256>>>();
    dim3 g(HWq / 256, Bq);
    fuse_kernel<<<g, 256>>>(x, inv_delay, ew_w, ew_b, out);
    gate_kernel<<<1, 128>>>(sta_w1, sta_w2, out, out_size);
    scale_kernel<<<(OUTQ + 255) / 256, 256>>>(out);
}